// round 2
// baseline (speedup 1.0000x reference)
#include <cuda_runtime.h>

// Haar DWT: x (8, 4096, 1024) fp32 -> cA, cD each (8, 2048, 1024)
// cA = (x_even + x_odd) * INV_SQRT2 ; cD = (x_even - x_odd) * INV_SQRT2
// d_out holds cA (16,777,216 floats) then cD.
//
// Pure HBM-streaming kernel: float4 vectorized, fully coalesced.
// Per-pair float4s along d: 1024/4 = 256.

#define INV_SQRT2F 0.70710678118654752440f

__global__ void dwt_haar_kernel(const float4* __restrict__ x,
                                float4* __restrict__ out,
                                int n4_out)  // float4s per output tensor
{
    int i = blockIdx.x * blockDim.x + threadIdx.x;
    if (i >= n4_out) return;

    int pair = i >> 8;        // (b*2048 + row) combined pair index
    int d4   = i & 255;       // float4 column within the 1024-wide row

    int e = pair * 512 + d4;  // even row float4 index; odd = e + 256

    float4 a = x[e];
    float4 b = x[e + 256];

    float4 cA, cD;
    cA.x = (a.x + b.x) * INV_SQRT2F;
    cA.y = (a.y + b.y) * INV_SQRT2F;
    cA.z = (a.z + b.z) * INV_SQRT2F;
    cA.w = (a.w + b.w) * INV_SQRT2F;

    cD.x = (a.x - b.x) * INV_SQRT2F;
    cD.y = (a.y - b.y) * INV_SQRT2F;
    cD.z = (a.z - b.z) * INV_SQRT2F;
    cD.w = (a.w - b.w) * INV_SQRT2F;

    out[i]          = cA;
    out[n4_out + i] = cD;
}

extern "C" void kernel_launch(void* const* d_in, const int* in_sizes, int n_in,
                              void* d_out, int out_size)
{
    const float4* x = (const float4*)d_in[0];
    float4* out     = (float4*)d_out;

    // out_size = 2 * 8*2048*1024 = 33,554,432 floats; per-tensor float4 count:
    int n4_out = (out_size / 2) / 4;   // 4,194,304

    const int threads = 256;
    int blocks = (n4_out + threads - 1) / threads;  // 16384

    dwt_haar_kernel<<<blocks, threads>>>(x, out, n4_out);
}

// round 3
// speedup vs baseline: 1.0081x; 1.0081x over previous
#include <cuda_runtime.h>

// Haar DWT: x (8, 4096, 1024) fp32 -> cA, cD each (8, 2048, 1024)
// cA = (x_even + x_odd) * INV_SQRT2 ; cD = (x_even - x_odd) * INV_SQRT2
// d_out = [cA | cD].
//
// R2: 2 float4-pairs per thread (same row pair, cols d4 and d4+128).
// 4 independent streaming loads issued before compute -> MLP=4/thread.
// All warp accesses fully coalesced; streaming cache hints (no reuse).

#define INV_SQRT2F 0.70710678118654752440f

__global__ void __launch_bounds__(256) dwt_haar_kernel(
    const float4* __restrict__ x,
    float4* __restrict__ out,
    int n4_out)  // float4s per output tensor (4,194,304)
{
    int i = blockIdx.x * blockDim.x + threadIdx.x;   // n4_out/2 threads
    int pair = i >> 7;        // (b*2048 + row) pair index
    int d4   = i & 127;       // float4 column (first half of 256-wide row)

    int e = pair * 512 + d4;  // even-row float4 base; odd row = +256

    // 4 independent loads, front-batched
    float4 a0 = __ldcs(&x[e]);
    float4 a1 = __ldcs(&x[e + 128]);
    float4 b0 = __ldcs(&x[e + 256]);
    float4 b1 = __ldcs(&x[e + 384]);

    float4 cA0, cD0, cA1, cD1;
    cA0.x = (a0.x + b0.x) * INV_SQRT2F;  cD0.x = (a0.x - b0.x) * INV_SQRT2F;
    cA0.y = (a0.y + b0.y) * INV_SQRT2F;  cD0.y = (a0.y - b0.y) * INV_SQRT2F;
    cA0.z = (a0.z + b0.z) * INV_SQRT2F;  cD0.z = (a0.z - b0.z) * INV_SQRT2F;
    cA0.w = (a0.w + b0.w) * INV_SQRT2F;  cD0.w = (a0.w - b0.w) * INV_SQRT2F;

    cA1.x = (a1.x + b1.x) * INV_SQRT2F;  cD1.x = (a1.x - b1.x) * INV_SQRT2F;
    cA1.y = (a1.y + b1.y) * INV_SQRT2F;  cD1.y = (a1.y - b1.y) * INV_SQRT2F;
    cA1.z = (a1.z + b1.z) * INV_SQRT2F;  cD1.z = (a1.z - b1.z) * INV_SQRT2F;
    cA1.w = (a1.w + b1.w) * INV_SQRT2F;  cD1.w = (a1.w - b1.w) * INV_SQRT2F;

    int o = pair * 256 + d4;  // output float4 index within cA
    __stcs(&out[o],                 cA0);
    __stcs(&out[o + 128],           cA1);
    __stcs(&out[n4_out + o],        cD0);
    __stcs(&out[n4_out + o + 128],  cD1);
}

extern "C" void kernel_launch(void* const* d_in, const int* in_sizes, int n_in,
                              void* d_out, int out_size)
{
    const float4* x = (const float4*)d_in[0];
    float4* out     = (float4*)d_out;

    int n4_out  = (out_size / 2) / 4;   // 4,194,304
    int threadsTotal = n4_out / 2;      // 2,097,152

    const int threads = 256;
    int blocks = threadsTotal / threads;  // 8192

    dwt_haar_kernel<<<blocks, threads>>>(x, out, n4_out);
}